// round 12
// baseline (speedup 1.0000x reference)
#include <cuda_runtime.h>
#include <cuda_fp16.h>
#include <math.h>
#include <stdint.h>

// Problem constants
#define BB 128   // batch
#define LL 128   // enc length
#define HE 1024  // enc hidden
#define HD 1024  // dec hidden
#define EE 512   // embed
#define AP 512   // attn proj
#define TT 64    // timesteps
#define G4 (4*HD)
#define QSPLIT 8
#define NCTA 128

// ---------------- device scratch ----------------
__device__ __half g_enc_projh[BB * LL * AP];
__device__ float g_qpart[QSPLIT * BB * AP];
__device__ float g_c1[BB * HD];
__device__ float g_c2[BB * HD];
__device__ float g_b1p[G4];
__device__ float g_b2p[G4];

__device__ __half g_h1ahi[TT * BB * HD], g_h1alo[TT * BB * HD];   // h1 archive
__device__ __half g_h1inithi[BB * HD], g_h1initlo[BB * HD];
__device__ __half g_h2hi[2][BB * HD], g_h2lo[2][BB * HD];
__device__ __half g_hp0hi[BB * HD], g_hp0lo[BB * HD];
__device__ __half g_ath[BB * HE];              // a_t single fp16 (non-recurrent)
__device__ __half g_caph[TT * BB * EE];        // captions single fp16
__device__ __half g_ench[BB * LL * HE];

#define WPOOL 20971520
__device__ __half g_wh[WPOOL];

#define O_ATTW ((size_t)0)
#define O_DHPW (O_ATTW + (size_t)HE * AP)
#define O_IH1  (O_DHPW + (size_t)HD * AP)
#define O_HH1  (O_IH1  + (size_t)(EE + HE) * G4)
#define O_IH2  (O_HH1  + (size_t)HD * G4)
#define O_HH2  (O_IH2  + (size_t)HD * G4)
#define O_LTW  (O_HH2  + (size_t)HD * G4)

// software grid barrier
__device__ unsigned g_bar_count = 0;
__device__ volatile unsigned g_bar_gen = 0;

__device__ __forceinline__ void grid_sync() {
    __threadfence();
    __syncthreads();
    if (threadIdx.x == 0) {
        unsigned gen = g_bar_gen;
        if (atomicAdd(&g_bar_count, 1u) == NCTA - 1u) {
            g_bar_count = 0;
            __threadfence();
            g_bar_gen = gen + 1;
        } else {
            while (g_bar_gen == gen) __nanosleep(32);
        }
    }
    __syncthreads();
}

__device__ __forceinline__ float fast_tanh(float x) {
    float e = __expf(2.0f * x);
    return 1.0f - __fdividef(2.0f, e + 1.0f);
}
__device__ __forceinline__ float fast_sigm(float x) {
    return __fdividef(1.0f, 1.0f + __expf(-x));
}
__device__ __forceinline__ float tanh_mufu(float x) {
    float y;
    asm("tanh.approx.f32 %0, %1;" : "=f"(y) : "f"(x));
    return y;
}

// ---------------- prep kernels ----------------
__global__ void init_state(const float* __restrict__ h1_0, const float* __restrict__ c1_0,
                           const float* __restrict__ h2_0, const float* __restrict__ c2_0) {
    int i = blockIdx.x * blockDim.x + threadIdx.x;
    if (i < BB * HD) {
        float h1 = h1_0[i], h2 = h2_0[i];
        __half a = __float2half_rn(h1);
        g_h1inithi[i] = a; g_h1initlo[i] = __float2half_rn(h1 - __half2float(a));
        __half b = __float2half_rn(h2);
        g_h2hi[0][i] = b; g_h2lo[0][i] = __float2half_rn(h2 - __half2float(b));
        g_c1[i] = c1_0[i];
        g_c2[i] = c2_0[i];
        g_hp0hi[i] = __float2half_rn(1.0f / (float)HE);
        g_hp0lo[i] = __float2half_rn(0.0f);
    }
}

__global__ void f32_cvt4(const float4* __restrict__ src, __half2* __restrict__ dst, int n4) {
    int i = blockIdx.x * 256 + threadIdx.x;
    if (i < n4) {
        float4 v = src[i];
        dst[2 * i]     = __halves2half2(__float2half_rn(v.x), __float2half_rn(v.y));
        dst[2 * i + 1] = __halves2half2(__float2half_rn(v.z), __float2half_rn(v.w));
    }
}

__global__ void f32_cvt_perm(const float* __restrict__ src, __half* __restrict__ dst, int K) {
    int i = blockIdx.x * 256 + threadIdx.x;
    if (i < K * G4) {
        int row = i / G4, cd = i % G4;
        int j = cd >> 2, gate = cd & 3;
        dst[i] = __float2half_rn(src[(size_t)row * G4 + gate * HD + j]);
    }
}

__global__ void bias_prep(const float* __restrict__ bi1, const float* __restrict__ bh1,
                          const float* __restrict__ bi2, const float* __restrict__ bh2) {
    int i = blockIdx.x * 256 + threadIdx.x;
    if (i < G4) {
        int j = i >> 2, gate = i & 3;
        g_b1p[i] = bi1[gate * HD + j] + bh1[gate * HD + j];
        g_b2p[i] = bi2[gate * HD + j] + bh2[gate * HD + j];
    }
}

// ---------------- fp16 GEMM tile with per-segment A-pass count ----------------
struct Seg2 {
    const __half* Ahi; const __half* Alo; int lda;
    const __half* B; int ldb;
    int K;
    int apass;   // 1: A single fp16; 2: A hi/lo
};
struct GemmArgs3 {
    Seg2 seg[3];
    int nseg;
    float* D; int ldd;
    const float* bias;
    int mode;                 // 0 plain f32, 1 tanh f32, 2 cell, 4 fp16 out
    float* cellC; __half* cellHhi; __half* cellHlo;
    __half* Dh;
    int zchunk;
};

#define PADA 40
#define PADB 72
#define STG 3
#define A_SET_H (STG * 64 * PADA)
#define B_SET_H (STG * 32 * PADB)
#define SET_H   (2 * A_SET_H + B_SET_H)
#define SMEM_BYTES (2 * SET_H * 2)

__device__ __forceinline__ uint32_t smem_u32(const void* p) {
    return (uint32_t)__cvta_generic_to_shared(p);
}
__device__ __forceinline__ void cp16(void* dst, const void* src) {
    asm volatile("cp.async.cg.shared.global [%0], [%1], 16;"
                 :: "r"(smem_u32(dst)), "l"(src));
}
__device__ __forceinline__ void ldsm_x4(uint32_t addr, uint32_t* r) {
    asm volatile("ldmatrix.sync.aligned.m8n8.x4.shared.b16 {%0,%1,%2,%3}, [%4];"
                 : "=r"(r[0]), "=r"(r[1]), "=r"(r[2]), "=r"(r[3]) : "r"(addr));
}
__device__ __forceinline__ void ldsm_x4_t(uint32_t addr, uint32_t& r0, uint32_t& r1,
                                          uint32_t& r2, uint32_t& r3) {
    asm volatile("ldmatrix.sync.aligned.m8n8.x4.trans.shared.b16 {%0,%1,%2,%3}, [%4];"
                 : "=r"(r0), "=r"(r1), "=r"(r2), "=r"(r3) : "r"(addr));
}
__device__ __forceinline__ void mma16816(float* c, const uint32_t* a, const uint32_t* b) {
    asm volatile(
        "mma.sync.aligned.m16n8k16.row.col.f32.f16.f16.f32 "
        "{%0,%1,%2,%3}, {%4,%5,%6,%7}, {%8,%9}, {%0,%1,%2,%3};"
        : "+f"(c[0]), "+f"(c[1]), "+f"(c[2]), "+f"(c[3])
        : "r"(a[0]), "r"(a[1]), "r"(a[2]), "r"(a[3]), "r"(b[0]), "r"(b[1]));
}
__device__ __forceinline__ void bar_set(int set) {
    asm volatile("bar.sync %0, 128;" :: "r"(set + 1) : "memory");
}

__device__ __forceinline__ int seg_of(const GemmArgs3& a, int g, int& k0) {
    int s = 0, rem = g;
    #pragma unroll
    for (int i = 0; i < 2; i++)
        if (s < a.nseg - 1 && rem >= (a.seg[s].K >> 5)) { rem -= a.seg[s].K >> 5; s++; }
    k0 = rem << 5;
    return s;
}

__device__ __forceinline__ void stage_tile(const GemmArgs3& a, int g, int bm, int bn, int stid,
                                           __half* AsH, __half* AsL, __half* Bs) {
    int k0;
    int s = seg_of(a, g, k0);
    const Seg2 sg = a.seg[s];
    #pragma unroll
    for (int i = 0; i < 2; i++) {
        int ch = stid + i * 128;
        int row = ch >> 2, c = (ch & 3) * 8;
        size_t off = (size_t)(bm + row) * sg.lda + k0 + c;
        cp16(AsH + row * PADA + c, sg.Ahi + off);
        if (sg.apass == 2) cp16(AsL + row * PADA + c, sg.Alo + off);
    }
    #pragma unroll
    for (int i = 0; i < 2; i++) {
        int ch = stid + i * 128;
        int row = ch >> 3, c = (ch & 7) * 8;
        size_t off = (size_t)(k0 + row) * sg.ldb + bn + c;
        cp16(Bs + row * PADB + c, sg.B + off);
    }
}

__device__ void gemm_tile(GemmArgs3 args, int bx, int by, int bz, char* smem_raw) {
    __half* base = (__half*)smem_raw;

    if (args.zchunk > 0) {
        args.seg[0].Ahi += (size_t)bz * args.zchunk;
        args.seg[0].Alo += (size_t)bz * args.zchunk;
        args.seg[0].B   += (size_t)bz * args.zchunk * args.seg[0].ldb;
        args.seg[0].K = args.zchunk;
        args.D += (size_t)bz * BB * args.ldd;
    }

    const int tid = threadIdx.x;
    const int lane = tid & 31;
    const int wid = tid >> 5;
    const int set = wid >> 2;
    const int swid = wid & 3;
    const int stid = tid & 127;
    const int wm = swid & 1;
    const int wn = swid >> 1;
    const int bm = by * 64;
    const int bn = bx * 64;

    __half* AsH = base + set * SET_H;
    __half* AsL = AsH + A_SET_H;
    __half* Bs  = AsL + A_SET_H;
    float* red = (float*)(base + SET_H);
    float* gsm = (float*)base;

    int ntile = 0;
    #pragma unroll
    for (int s = 0; s < 3; s++) if (s < args.nseg) ntile += args.seg[s].K >> 5;
    const int cnt = (ntile - set + 1) >> 1;

    float acc[2][4][4];
    #pragma unroll
    for (int i = 0; i < 2; i++)
        #pragma unroll
        for (int j = 0; j < 4; j++)
            #pragma unroll
            for (int k = 0; k < 4; k++) acc[i][j][k] = 0.0f;

    const int a_r = lane & 15;
    const int a_c = (lane >> 4) << 3;
    const int b_r = (lane & 7) + ((lane >> 3) & 1) * 8;
    const int b_c = (lane >> 4) << 3;

    if (cnt > 0)
        stage_tile(args, set, bm, bn, stid, AsH, AsL, Bs);
    asm volatile("cp.async.commit_group;");
    if (cnt > 1)
        stage_tile(args, 2 + set, bm, bn, stid,
                   AsH + 64 * PADA, AsL + 64 * PADA, Bs + 32 * PADB);
    asm volatile("cp.async.commit_group;");

    for (int j = 0; j < cnt; j++) {
        asm volatile("cp.async.wait_group 1;");
        bar_set(set);
        {
            int p = (j + 2) % 3;
            if (j + 2 < cnt)
                stage_tile(args, 2 * (j + 2) + set, bm, bn, stid,
                           AsH + p * 64 * PADA, AsL + p * 64 * PADA, Bs + p * 32 * PADB);
            asm volatile("cp.async.commit_group;");
        }
        // per-tile apass from segment
        int k0dummy;
        const int ap = args.seg[seg_of(args, 2 * j + set, k0dummy)].apass;

        const int q = j % 3;
        const __half* cAH = AsH + q * 64 * PADA;
        const __half* cAL = AsL + q * 64 * PADA;
        const __half* cB  = Bs + q * 32 * PADB;
        #pragma unroll
        for (int kk = 0; kk < 32; kk += 16) {
            uint32_t ah[2][4], al[2][4];
            #pragma unroll
            for (int mt = 0; mt < 2; mt++) {
                int rowoff = (wm * 32 + mt * 16 + a_r) * PADA + kk + a_c;
                ldsm_x4(smem_u32(&cAH[rowoff]), ah[mt]);
                if (ap == 2) ldsm_x4(smem_u32(&cAL[rowoff]), al[mt]);
            }
            uint32_t bh[4][2];
            #pragma unroll
            for (int gi = 0; gi < 2; gi++) {
                int boff = (kk + b_r) * PADB + wn * 32 + gi * 16 + b_c;
                ldsm_x4_t(smem_u32(&cB[boff]),
                          bh[gi * 2][0], bh[gi * 2][1], bh[gi * 2 + 1][0], bh[gi * 2 + 1][1]);
            }
            #pragma unroll
            for (int mt = 0; mt < 2; mt++)
                #pragma unroll
                for (int nt = 0; nt < 4; nt++) {
                    mma16816(acc[mt][nt], ah[mt], bh[nt]);
                    if (ap == 2) mma16816(acc[mt][nt], al[mt], bh[nt]);
                }
        }
    }

    asm volatile("cp.async.wait_group 0;");
    __syncthreads();

    if (set == 1) {
        float* r = red + swid * 1024 + lane * 32;
        #pragma unroll
        for (int mt = 0; mt < 2; mt++)
            #pragma unroll
            for (int nt = 0; nt < 4; nt++)
                #pragma unroll
                for (int k = 0; k < 4; k++)
                    r[mt * 16 + nt * 4 + k] = acc[mt][nt][k];
    }
    __syncthreads();

    if (args.mode != 2) {
        if (set == 0) {
            const float* r = red + swid * 1024 + lane * 32;
            const int do_tanh = (args.mode == 1);
            #pragma unroll
            for (int mt = 0; mt < 2; mt++) {
                int r0 = bm + wm * 32 + mt * 16 + (lane >> 2);
                #pragma unroll
                for (int nt = 0; nt < 4; nt++) {
                    int c0 = bn + wn * 32 + nt * 8 + (lane & 3) * 2;
                    float bia0 = 0.0f, bia1 = 0.0f;
                    if (args.bias) { bia0 = args.bias[c0]; bia1 = args.bias[c0 + 1]; }
                    float v00 = acc[mt][nt][0] + r[mt * 16 + nt * 4 + 0] + bia0;
                    float v01 = acc[mt][nt][1] + r[mt * 16 + nt * 4 + 1] + bia1;
                    float v10 = acc[mt][nt][2] + r[mt * 16 + nt * 4 + 2] + bia0;
                    float v11 = acc[mt][nt][3] + r[mt * 16 + nt * 4 + 3] + bia1;
                    if (do_tanh) {
                        v00 = fast_tanh(v00); v01 = fast_tanh(v01);
                        v10 = fast_tanh(v10); v11 = fast_tanh(v11);
                    }
                    if (args.mode == 4) {
                        *reinterpret_cast<__half2*>(args.Dh + (size_t)r0 * args.ldd + c0) =
                            __halves2half2(__float2half_rn(v00), __float2half_rn(v01));
                        *reinterpret_cast<__half2*>(args.Dh + (size_t)(r0 + 8) * args.ldd + c0) =
                            __halves2half2(__float2half_rn(v10), __float2half_rn(v11));
                    } else {
                        args.D[(size_t)r0 * args.ldd + c0] = v00;
                        args.D[(size_t)r0 * args.ldd + c0 + 1] = v01;
                        args.D[(size_t)(r0 + 8) * args.ldd + c0] = v10;
                        args.D[(size_t)(r0 + 8) * args.ldd + c0 + 1] = v11;
                    }
                }
            }
        }
    } else {
        if (set == 0) {
            const float* r = red + swid * 1024 + lane * 32;
            #pragma unroll
            for (int mt = 0; mt < 2; mt++) {
                int lr = wm * 32 + mt * 16 + (lane >> 2);
                #pragma unroll
                for (int nt = 0; nt < 4; nt++) {
                    int lc = wn * 32 + nt * 8 + (lane & 3) * 2;
                    float bia0 = args.bias[bn + lc];
                    float bia1 = args.bias[bn + lc + 1];
                    gsm[lr * 64 + lc]            = acc[mt][nt][0] + r[mt * 16 + nt * 4 + 0] + bia0;
                    gsm[lr * 64 + lc + 1]        = acc[mt][nt][1] + r[mt * 16 + nt * 4 + 1] + bia1;
                    gsm[(lr + 8) * 64 + lc]      = acc[mt][nt][2] + r[mt * 16 + nt * 4 + 2] + bia0;
                    gsm[(lr + 8) * 64 + lc + 1]  = acc[mt][nt][3] + r[mt * 16 + nt * 4 + 3] + bia1;
                }
            }
        }
        __syncthreads();
        #pragma unroll
        for (int it = 0; it < 4; it++) {
            int idx = tid + it * 256;
            int row = idx >> 4;
            int u = idx & 15;
            float4 gq = *reinterpret_cast<float4*>(&gsm[row * 64 + u * 4]);  // i,f,g,o
            int gr = bm + row;
            int ju = (bn >> 2) + u;
            size_t hix = (size_t)gr * HD + ju;
            float cn = fast_sigm(gq.y) * args.cellC[hix] + fast_sigm(gq.x) * fast_tanh(gq.z);
            float hn = fast_sigm(gq.w) * fast_tanh(cn);
            args.cellC[hix] = cn;
            __half hh = __float2half_rn(hn);
            args.cellHhi[hix] = hh;
            args.cellHlo[hix] = __float2half_rn(hn - __half2float(hh));
        }
    }
    __syncthreads();
}

__global__ void __launch_bounds__(256)
gemm_f16s(GemmArgs3 args) {
    extern __shared__ char smem_raw[];
    gemm_tile(args, blockIdx.x, blockIdx.y, blockIdx.z, smem_raw);
}

// ---------------- attention phase (device fn, 256 threads, CTA = batch row) ----------------
__device__ void attn_phase(char* smem_raw, int b,
                           const float* __restrict__ corr_w,
                           const float* __restrict__ corr_b,
                           const int* __restrict__ mask,
                           const float* __restrict__ dhp_b) {
    const int tid = threadIdx.x;
    const int lane = tid & 31;
    const int warp = tid >> 5;     // 8 warps

    float* sm_q = (float*)smem_raw;
    float* sm_e = sm_q + AP;
    float* sm_a = sm_e + LL;

    for (int i = tid; i < AP; i += 256) {
        float s = dhp_b[i];
        #pragma unroll
        for (int z = 0; z < QSPLIT; z++)
            s += __ldcg(&g_qpart[(size_t)z * BB * AP + b * AP + i]);
        sm_q[i] = s;
    }
    __syncthreads();

    for (int l = warp; l < LL; l += 8) {
        const __half* ep = g_enc_projh + ((size_t)b * LL + l) * AP;
        float s = 0.0f;
        #pragma unroll
        for (int k = 0; k < 8; k++) {
            int ap = lane * 2 + k * 64;
            __half2 v = *reinterpret_cast<const __half2*>(ep + ap);
            s += tanh_mufu(__low2float(v) + sm_q[ap]) * corr_w[ap];
            s += tanh_mufu(__high2float(v) + sm_q[ap + 1]) * corr_w[ap + 1];
        }
        #pragma unroll
        for (int o = 16; o; o >>= 1) s += __shfl_down_sync(0xffffffffu, s, o);
        if (lane == 0) {
            float v = s + corr_b[0];
            if (mask[b * LL + l] != 0) v = -INFINITY;
            sm_e[l] = v;
        }
    }
    __syncthreads();

    if (warp == 0) {
        float m = -INFINITY;
        #pragma unroll
        for (int i = lane; i < LL; i += 32) m = fmaxf(m, sm_e[i]);
        #pragma unroll
        for (int o = 16; o; o >>= 1) m = fmaxf(m, __shfl_xor_sync(0xffffffffu, m, o));
        float sum = 0.0f;
        #pragma unroll
        for (int i = lane; i < LL; i += 32) sum += __expf(sm_e[i] - m);
        #pragma unroll
        for (int o = 16; o; o >>= 1) sum += __shfl_xor_sync(0xffffffffu, sum, o);
        float inv = __fdividef(1.0f, sum);
        #pragma unroll
        for (int i = lane; i < LL; i += 32) sm_a[i] = __expf(sm_e[i] - m) * inv;
    }
    __syncthreads();

    // context -> a_t single fp16
    {
        int h0 = tid * 4;
        const __half* eb = g_ench + (size_t)b * LL * HE + h0;
        float a0 = 0.0f, a1 = 0.0f, a2 = 0.0f, a3 = 0.0f;
        #pragma unroll 4
        for (int l = 0; l < LL; l++) {
            const __half2* p = reinterpret_cast<const __half2*>(eb + (size_t)l * HE);
            __half2 v0 = p[0], v1 = p[1];
            float al = sm_a[l];
            a0 = fmaf(al, __low2float(v0), a0);
            a1 = fmaf(al, __high2float(v0), a1);
            a2 = fmaf(al, __low2float(v1), a2);
            a3 = fmaf(al, __high2float(v1), a3);
        }
        __half2* dh = reinterpret_cast<__half2*>(g_ath + (size_t)b * HE + h0);
        dh[0] = __halves2half2(__float2half_rn(a0), __float2half_rn(a1));
        dh[1] = __halves2half2(__float2half_rn(a2), __float2half_rn(a3));
    }
    __syncthreads();
}

// ---------------- persistent decoder loop ----------------
__global__ void __launch_bounds__(256)
decoder_loop(const float* __restrict__ corr_w, const float* __restrict__ corr_b,
             const int* __restrict__ mask, const float* __restrict__ dhp_b) {
    extern __shared__ char smem[];
    const int cta = blockIdx.x;

    for (int t = 0; t < TT; t++) {
        const int cur = t & 1, nxt = cur ^ 1;
        const __half* hp_hi = (t == 0) ? g_hp0hi : g_h2hi[cur];
        const __half* hp_lo = (t == 0) ? g_hp0lo : g_h2lo[cur];
        const __half* h1p_hi = (t == 0) ? g_h1inithi : g_h1ahi + (size_t)(t - 1) * BB * HD;
        const __half* h1p_lo = (t == 0) ? g_h1initlo : g_h1alo + (size_t)(t - 1) * BB * HD;
        __half* h1c_hi = g_h1ahi + (size_t)t * BB * HD;
        __half* h1c_lo = g_h1alo + (size_t)t * BB * HD;

        // phase 1: q partials (apass=1: scores are error-tolerant)
        {
            GemmArgs3 a = {};
            a.seg[0] = {hp_hi, hp_lo, HD, g_wh + O_DHPW, AP, HD, 1};
            a.nseg = 1; a.D = g_qpart; a.ldd = AP; a.bias = nullptr; a.mode = 0;
            a.zchunk = HD / QSPLIT;
            int z = cta >> 4, rem = cta & 15;
            gemm_tile(a, rem & 7, rem >> 3, z, smem);
        }
        grid_sync();

        // phase 2: attention
        attn_phase(smem, cta, corr_w, corr_b, mask, dhp_b);
        grid_sync();

        // phase 3: gates1 + cell1 (cap:1, a_t:1, h1:2)
        {
            GemmArgs3 a = {};
            a.seg[0] = {g_caph + (size_t)t * BB * EE, nullptr, EE, g_wh + O_IH1, G4, EE, 1};
            a.seg[1] = {g_ath, nullptr, HE, g_wh + O_IH1 + (size_t)EE * G4, G4, HE, 1};
            a.seg[2] = {h1p_hi, h1p_lo, HD, g_wh + O_HH1, G4, HD, 2};
            a.nseg = 3; a.bias = g_b1p; a.mode = 2; a.zchunk = 0;
            a.cellC = g_c1; a.cellHhi = h1c_hi; a.cellHlo = h1c_lo;
            gemm_tile(a, cta & 63, cta >> 6, 0, smem);
        }
        grid_sync();

        // phase 4: gates2 + cell2 (h1:2, h2:2 — recurrent, keep hi/lo)
        {
            GemmArgs3 a = {};
            a.seg[0] = {h1c_hi, h1c_lo, HD, g_wh + O_IH2, G4, HD, 2};
            a.seg[1] = {g_h2hi[cur], g_h2lo[cur], HD, g_wh + O_HH2, G4, HD, 2};
            a.nseg = 2; a.bias = g_b2p; a.mode = 2; a.zchunk = 0;
            a.cellC = g_c2; a.cellHhi = g_h2hi[nxt]; a.cellHlo = g_h2lo[nxt];
            gemm_tile(a, cta & 63, cta >> 6, 0, smem);
        }
        grid_sync();
    }
}

// ---------------- launch ----------------
extern "C" void kernel_launch(void* const* d_in, const int* in_sizes, int n_in,
                              void* d_out, int out_size) {
    const float* enc      = (const float*)d_in[0];
    const int*   mask     = (const int*)  d_in[1];
    const float* h1_0     = (const float*)d_in[2];
    const float* c1_0     = (const float*)d_in[3];
    const float* h2_0     = (const float*)d_in[4];
    const float* c2_0     = (const float*)d_in[5];
    const float* captions = (const float*)d_in[6];
    const float* att_W    = (const float*)d_in[7];
    const float* att_b    = (const float*)d_in[8];
    const float* dhp_W    = (const float*)d_in[9];
    const float* dhp_b    = (const float*)d_in[10];
    const float* corr_w   = (const float*)d_in[11];
    const float* corr_b   = (const float*)d_in[12];
    const float* lt_W     = (const float*)d_in[13];
    const float* lt_b     = (const float*)d_in[14];
    const float* W_ih1    = (const float*)d_in[15];
    const float* W_hh1    = (const float*)d_in[16];
    const float* b_ih1    = (const float*)d_in[17];
    const float* b_hh1    = (const float*)d_in[18];
    const float* W_ih2    = (const float*)d_in[19];
    const float* W_hh2    = (const float*)d_in[20];
    const float* b_ih2    = (const float*)d_in[21];
    const float* b_hh2    = (const float*)d_in[22];
    float* out = (float*)d_out;

    cudaFuncSetAttribute(gemm_f16s, cudaFuncAttributeMaxDynamicSharedMemorySize, SMEM_BYTES);
    cudaFuncSetAttribute(decoder_loop, cudaFuncAttributeMaxDynamicSharedMemorySize, SMEM_BYTES);

    __half *p_encprojh, *p_wh, *p_ench, *p_caph, *p_h1ahi, *p_h1alo;
    cudaGetSymbolAddress((void**)&p_encprojh, g_enc_projh);
    cudaGetSymbolAddress((void**)&p_wh,    g_wh);
    cudaGetSymbolAddress((void**)&p_ench,  g_ench);
    cudaGetSymbolAddress((void**)&p_caph,  g_caph);
    cudaGetSymbolAddress((void**)&p_h1ahi, g_h1ahi);
    cudaGetSymbolAddress((void**)&p_h1alo, g_h1alo);

    // ---- prep ----
    f32_cvt4<<<(HE * AP / 4 + 255) / 256, 256>>>(
        (const float4*)att_W, (__half2*)(p_wh + O_ATTW), HE * AP / 4);
    f32_cvt4<<<(HD * AP / 4 + 255) / 256, 256>>>(
        (const float4*)dhp_W, (__half2*)(p_wh + O_DHPW), HD * AP / 4);
    f32_cvt4<<<(HD * HD / 4 + 255) / 256, 256>>>(
        (const float4*)lt_W, (__half2*)(p_wh + O_LTW), HD * HD / 4);
    f32_cvt4<<<(BB * LL * HE / 4 + 255) / 256, 256>>>(
        (const float4*)enc, (__half2*)p_ench, BB * LL * HE / 4);
    f32_cvt4<<<(TT * BB * EE / 4 + 255) / 256, 256>>>(
        (const float4*)captions, (__half2*)p_caph, TT * BB * EE / 4);
    f32_cvt_perm<<<((EE + HE) * G4 + 255) / 256, 256>>>(W_ih1, p_wh + O_IH1, EE + HE);
    f32_cvt_perm<<<(HD * G4 + 255) / 256, 256>>>(W_hh1, p_wh + O_HH1, HD);
    f32_cvt_perm<<<(HD * G4 + 255) / 256, 256>>>(W_ih2, p_wh + O_IH2, HD);
    f32_cvt_perm<<<(HD * G4 + 255) / 256, 256>>>(W_hh2, p_wh + O_HH2, HD);
    bias_prep<<<(G4 + 255) / 256, 256>>>(b_ih1, b_hh1, b_ih2, b_hh2);
    init_state<<<(BB * HD + 255) / 256, 256>>>(h1_0, c1_0, h2_0, c2_0);

    // enc_proj = enc @ att_W + att_b (fp16 out, 1 A-pass)
    {
        GemmArgs3 a = {};
        a.seg[0] = {p_ench, nullptr, HE, p_wh + O_ATTW, AP, HE, 1};
        a.nseg = 1; a.ldd = AP; a.bias = att_b; a.mode = 4;
        a.Dh = p_encprojh; a.zchunk = 0;
        gemm_f16s<<<dim3(AP / 64, (BB * LL) / 64), 256, SMEM_BYTES>>>(a);
    }

    // full 64-step decoder loop: ONE persistent kernel
    decoder_loop<<<NCTA, 256, SMEM_BYTES>>>(corr_w, corr_b, mask, dhp_b);

    // final batched out-projection: out = tanh(h1_archive @ lt_W + lt_b), hi/lo (direct output)
    {
        GemmArgs3 a = {};
        a.seg[0] = {p_h1ahi, p_h1alo, HD, p_wh + O_LTW, HD, HD, 2};
        a.nseg = 1; a.D = out; a.ldd = HD; a.bias = lt_b; a.mode = 1; a.zchunk = 0;
        gemm_f16s<<<dim3(HD / 64, (TT * BB) / 64), 256, SMEM_BYTES>>>(a);
    }

    (void)in_sizes; (void)n_in; (void)out_size;
}

// round 13
// speedup vs baseline: 1.1226x; 1.1226x over previous
#include <cuda_runtime.h>
#include <cuda_fp16.h>
#include <math.h>
#include <stdint.h>

// Problem constants
#define BB 128   // batch
#define LL 128   // enc length
#define HE 1024  // enc hidden
#define HD 1024  // dec hidden
#define EE 512   // embed
#define AP 512   // attn proj
#define TT 64    // timesteps
#define G4 (4*HD)
#define QSPLIT 8
#define NCTA 128

// ---------------- device scratch ----------------
__device__ __half g_enc_projh[BB * LL * AP];   // fp16 enc_proj (read-only in loop)
__device__ float g_qpart[QSPLIT * BB * AP];
__device__ float g_c1[BB * HD];
__device__ float g_c2[BB * HD];
__device__ float g_b1p[G4];
__device__ float g_b2p[G4];

__device__ __half g_h1ahi[TT * BB * HD], g_h1alo[TT * BB * HD];   // h1 archive
__device__ __half g_h1inithi[BB * HD], g_h1initlo[BB * HD];
__device__ __half g_h2hi[2][BB * HD], g_h2lo[2][BB * HD];
__device__ __half g_hp0hi[BB * HD], g_hp0lo[BB * HD];
__device__ __half g_athi[BB * HE], g_atlo[BB * HE];
__device__ __half g_caphi[TT * BB * EE], g_caplo[TT * BB * EE];
__device__ __half g_ench[BB * LL * HE];

#define WPOOL 20971520
__device__ __half g_wh[WPOOL];

// weight pool offsets (compile-time)
#define O_ATTW ((size_t)0)
#define O_DHPW (O_ATTW + (size_t)HE * AP)
#define O_IH1  (O_DHPW + (size_t)HD * AP)
#define O_HH1  (O_IH1  + (size_t)(EE + HE) * G4)
#define O_IH2  (O_HH1  + (size_t)HD * G4)
#define O_HH2  (O_IH2  + (size_t)HD * G4)
#define O_LTW  (O_HH2  + (size_t)HD * G4)

// software grid barrier
__device__ unsigned g_bar_count = 0;
__device__ volatile unsigned g_bar_gen = 0;

__device__ __forceinline__ void grid_sync() {
    __threadfence();
    __syncthreads();
    if (threadIdx.x == 0) {
        unsigned gen = g_bar_gen;
        if (atomicAdd(&g_bar_count, 1u) == NCTA - 1u) {
            g_bar_count = 0;
            __threadfence();
            g_bar_gen = gen + 1;
        } else {
            while (g_bar_gen == gen) __nanosleep(32);
        }
    }
    __syncthreads();
}

__device__ __forceinline__ float fast_tanh(float x) {
    float e = __expf(2.0f * x);
    return 1.0f - __fdividef(2.0f, e + 1.0f);
}
__device__ __forceinline__ float fast_sigm(float x) {
    return __fdividef(1.0f, 1.0f + __expf(-x));
}
__device__ __forceinline__ float tanh_mufu(float x) {
    float y;
    asm("tanh.approx.f32 %0, %1;" : "=f"(y) : "f"(x));
    return y;
}

// ---------------- prep kernels ----------------
__global__ void init_state(const float* __restrict__ h1_0, const float* __restrict__ c1_0,
                           const float* __restrict__ h2_0, const float* __restrict__ c2_0) {
    int i = blockIdx.x * blockDim.x + threadIdx.x;
    if (i < BB * HD) {
        float h1 = h1_0[i], h2 = h2_0[i];
        __half a = __float2half_rn(h1);
        g_h1inithi[i] = a; g_h1initlo[i] = __float2half_rn(h1 - __half2float(a));
        __half b = __float2half_rn(h2);
        g_h2hi[0][i] = b; g_h2lo[0][i] = __float2half_rn(h2 - __half2float(b));
        g_c1[i] = c1_0[i];
        g_c2[i] = c2_0[i];
        g_hp0hi[i] = __float2half_rn(1.0f / (float)HE);
        g_hp0lo[i] = __float2half_rn(0.0f);
    }
}

__global__ void f32_split4(const float4* __restrict__ src,
                           __half2* __restrict__ hi,
                           __half2* __restrict__ lo, int n4) {
    int i = blockIdx.x * 256 + threadIdx.x;
    if (i < n4) {
        float4 v = src[i];
        __half h0 = __float2half_rn(v.x);
        __half h1 = __float2half_rn(v.y);
        __half h2 = __float2half_rn(v.z);
        __half h3 = __float2half_rn(v.w);
        hi[2 * i]     = __halves2half2(h0, h1);
        hi[2 * i + 1] = __halves2half2(h2, h3);
        lo[2 * i]     = __halves2half2(
            __float2half_rn(v.x - __half2float(h0)),
            __float2half_rn(v.y - __half2float(h1)));
        lo[2 * i + 1] = __halves2half2(
            __float2half_rn(v.z - __half2float(h2)),
            __float2half_rn(v.w - __half2float(h3)));
    }
}

__global__ void f32_cvt4(const float4* __restrict__ src, __half2* __restrict__ dst, int n4) {
    int i = blockIdx.x * 256 + threadIdx.x;
    if (i < n4) {
        float4 v = src[i];
        dst[2 * i]     = __halves2half2(__float2half_rn(v.x), __float2half_rn(v.y));
        dst[2 * i + 1] = __halves2half2(__float2half_rn(v.z), __float2half_rn(v.w));
    }
}

__global__ void f32_cvt_perm(const float* __restrict__ src, __half* __restrict__ dst, int K) {
    int i = blockIdx.x * 256 + threadIdx.x;
    if (i < K * G4) {
        int row = i / G4, cd = i % G4;
        int j = cd >> 2, gate = cd & 3;
        dst[i] = __float2half_rn(src[(size_t)row * G4 + gate * HD + j]);
    }
}

__global__ void bias_prep(const float* __restrict__ bi1, const float* __restrict__ bh1,
                          const float* __restrict__ bi2, const float* __restrict__ bh2) {
    int i = blockIdx.x * 256 + threadIdx.x;
    if (i < G4) {
        int j = i >> 2, gate = i & 3;
        g_b1p[i] = bi1[gate * HD + j] + bh1[gate * HD + j];
        g_b2p[i] = bi2[gate * HD + j] + bh2[gate * HD + j];
    }
}

// ---------------- fp16 split-A tensor-core GEMM tile (device fn) ----------------
struct Seg2 {
    const __half* Ahi; const __half* Alo; int lda;
    const __half* B; int ldb;
    int K;
};
struct GemmArgs3 {
    Seg2 seg[3];
    int nseg;
    int apass;                // 1 or 2 A-passes (UNIFORM per kernel call)
    float* D; int ldd;
    const float* bias;
    int mode;                 // 0 plain f32, 1 tanh f32, 2 cell, 4 fp16 out
    float* cellC; __half* cellHhi; __half* cellHlo;
    __half* Dh;
    int zchunk;
};

#define PADA 40
#define PADB 72
#define STG 3
#define A_SET_H (STG * 64 * PADA)
#define B_SET_H (STG * 32 * PADB)
#define SET_H   (2 * A_SET_H + B_SET_H)
#define SMEM_BYTES (2 * SET_H * 2)

__device__ __forceinline__ uint32_t smem_u32(const void* p) {
    return (uint32_t)__cvta_generic_to_shared(p);
}
// cg variant: bypass L1 (persistent kernel; cross-CTA producer/consumer)
__device__ __forceinline__ void cp16(void* dst, const void* src) {
    asm volatile("cp.async.cg.shared.global [%0], [%1], 16;"
                 :: "r"(smem_u32(dst)), "l"(src));
}
__device__ __forceinline__ void ldsm_x4(uint32_t addr, uint32_t* r) {
    asm volatile("ldmatrix.sync.aligned.m8n8.x4.shared.b16 {%0,%1,%2,%3}, [%4];"
                 : "=r"(r[0]), "=r"(r[1]), "=r"(r[2]), "=r"(r[3]) : "r"(addr));
}
__device__ __forceinline__ void ldsm_x4_t(uint32_t addr, uint32_t& r0, uint32_t& r1,
                                          uint32_t& r2, uint32_t& r3) {
    asm volatile("ldmatrix.sync.aligned.m8n8.x4.trans.shared.b16 {%0,%1,%2,%3}, [%4];"
                 : "=r"(r0), "=r"(r1), "=r"(r2), "=r"(r3) : "r"(addr));
}
__device__ __forceinline__ void mma16816(float* c, const uint32_t* a, const uint32_t* b) {
    asm volatile(
        "mma.sync.aligned.m16n8k16.row.col.f32.f16.f16.f32 "
        "{%0,%1,%2,%3}, {%4,%5,%6,%7}, {%8,%9}, {%0,%1,%2,%3};"
        : "+f"(c[0]), "+f"(c[1]), "+f"(c[2]), "+f"(c[3])
        : "r"(a[0]), "r"(a[1]), "r"(a[2]), "r"(a[3]), "r"(b[0]), "r"(b[1]));
}
__device__ __forceinline__ void bar_set(int set) {
    asm volatile("bar.sync %0, 128;" :: "r"(set + 1) : "memory");
}

__device__ __forceinline__ void stage_tile(const GemmArgs3& a, int g, int bm, int bn, int stid,
                                           __half* AsH, __half* AsL, __half* Bs) {
    int s = 0, rem = g;
    #pragma unroll
    for (int i = 0; i < 2; i++)
        if (s < a.nseg - 1 && rem >= (a.seg[s].K >> 5)) { rem -= a.seg[s].K >> 5; s++; }
    const Seg2 sg = a.seg[s];
    const int k0 = rem << 5;
    #pragma unroll
    for (int i = 0; i < 2; i++) {
        int ch = stid + i * 128;
        int row = ch >> 2, c = (ch & 3) * 8;
        size_t off = (size_t)(bm + row) * sg.lda + k0 + c;
        cp16(AsH + row * PADA + c, sg.Ahi + off);
        if (a.apass == 2) cp16(AsL + row * PADA + c, sg.Alo + off);
    }
    #pragma unroll
    for (int i = 0; i < 2; i++) {
        int ch = stid + i * 128;
        int row = ch >> 3, c = (ch & 7) * 8;
        size_t off = (size_t)(k0 + row) * sg.ldb + bn + c;
        cp16(Bs + row * PADB + c, sg.B + off);
    }
}

__device__ void gemm_tile(GemmArgs3 args, int bx, int by, int bz, char* smem_raw) {
    __half* base = (__half*)smem_raw;

    if (args.zchunk > 0) {
        args.seg[0].Ahi += (size_t)bz * args.zchunk;
        args.seg[0].Alo += (size_t)bz * args.zchunk;
        args.seg[0].B   += (size_t)bz * args.zchunk * args.seg[0].ldb;
        args.seg[0].K = args.zchunk;
        args.D += (size_t)bz * BB * args.ldd;
    }

    const int tid = threadIdx.x;
    const int lane = tid & 31;
    const int wid = tid >> 5;
    const int set = wid >> 2;
    const int swid = wid & 3;
    const int stid = tid & 127;
    const int wm = swid & 1;
    const int wn = swid >> 1;
    const int bm = by * 64;
    const int bn = bx * 64;

    __half* AsH = base + set * SET_H;
    __half* AsL = AsH + A_SET_H;
    __half* Bs  = AsL + A_SET_H;
    float* red = (float*)(base + SET_H);
    float* gsm = (float*)base;

    int ntile = 0;
    #pragma unroll
    for (int s = 0; s < 3; s++) if (s < args.nseg) ntile += args.seg[s].K >> 5;
    const int cnt = (ntile - set + 1) >> 1;

    float acc[2][4][4];
    #pragma unroll
    for (int i = 0; i < 2; i++)
        #pragma unroll
        for (int j = 0; j < 4; j++)
            #pragma unroll
            for (int k = 0; k < 4; k++) acc[i][j][k] = 0.0f;

    const int a_r = lane & 15;
    const int a_c = (lane >> 4) << 3;
    const int b_r = (lane & 7) + ((lane >> 3) & 1) * 8;
    const int b_c = (lane >> 4) << 3;

    if (cnt > 0)
        stage_tile(args, set, bm, bn, stid, AsH, AsL, Bs);
    asm volatile("cp.async.commit_group;");
    if (cnt > 1)
        stage_tile(args, 2 + set, bm, bn, stid,
                   AsH + 64 * PADA, AsL + 64 * PADA, Bs + 32 * PADB);
    asm volatile("cp.async.commit_group;");

    for (int j = 0; j < cnt; j++) {
        asm volatile("cp.async.wait_group 1;");
        bar_set(set);
        {
            int p = (j + 2) % 3;
            if (j + 2 < cnt)
                stage_tile(args, 2 * (j + 2) + set, bm, bn, stid,
                           AsH + p * 64 * PADA, AsL + p * 64 * PADA, Bs + p * 32 * PADB);
            asm volatile("cp.async.commit_group;");
        }
        const int q = j % 3;
        const __half* cAH = AsH + q * 64 * PADA;
        const __half* cAL = AsL + q * 64 * PADA;
        const __half* cB  = Bs + q * 32 * PADB;
        #pragma unroll
        for (int kk = 0; kk < 32; kk += 16) {
            uint32_t ah[2][4], al[2][4];
            #pragma unroll
            for (int mt = 0; mt < 2; mt++) {
                int rowoff = (wm * 32 + mt * 16 + a_r) * PADA + kk + a_c;
                ldsm_x4(smem_u32(&cAH[rowoff]), ah[mt]);
                if (args.apass == 2) ldsm_x4(smem_u32(&cAL[rowoff]), al[mt]);
            }
            uint32_t bh[4][2];
            #pragma unroll
            for (int gi = 0; gi < 2; gi++) {
                int boff = (kk + b_r) * PADB + wn * 32 + gi * 16 + b_c;
                ldsm_x4_t(smem_u32(&cB[boff]),
                          bh[gi * 2][0], bh[gi * 2][1], bh[gi * 2 + 1][0], bh[gi * 2 + 1][1]);
            }
            #pragma unroll
            for (int mt = 0; mt < 2; mt++)
                #pragma unroll
                for (int nt = 0; nt < 4; nt++) {
                    mma16816(acc[mt][nt], ah[mt], bh[nt]);
                    if (args.apass == 2) mma16816(acc[mt][nt], al[mt], bh[nt]);
                }
        }
    }

    asm volatile("cp.async.wait_group 0;");
    __syncthreads();

    if (set == 1) {
        float* r = red + swid * 1024 + lane * 32;
        #pragma unroll
        for (int mt = 0; mt < 2; mt++)
            #pragma unroll
            for (int nt = 0; nt < 4; nt++)
                #pragma unroll
                for (int k = 0; k < 4; k++)
                    r[mt * 16 + nt * 4 + k] = acc[mt][nt][k];
    }
    __syncthreads();

    if (args.mode != 2) {
        if (set == 0) {
            const float* r = red + swid * 1024 + lane * 32;
            const int do_tanh = (args.mode == 1);
            #pragma unroll
            for (int mt = 0; mt < 2; mt++) {
                int r0 = bm + wm * 32 + mt * 16 + (lane >> 2);
                #pragma unroll
                for (int nt = 0; nt < 4; nt++) {
                    int c0 = bn + wn * 32 + nt * 8 + (lane & 3) * 2;
                    float bia0 = 0.0f, bia1 = 0.0f;
                    if (args.bias) { bia0 = args.bias[c0]; bia1 = args.bias[c0 + 1]; }
                    float v00 = acc[mt][nt][0] + r[mt * 16 + nt * 4 + 0] + bia0;
                    float v01 = acc[mt][nt][1] + r[mt * 16 + nt * 4 + 1] + bia1;
                    float v10 = acc[mt][nt][2] + r[mt * 16 + nt * 4 + 2] + bia0;
                    float v11 = acc[mt][nt][3] + r[mt * 16 + nt * 4 + 3] + bia1;
                    if (do_tanh) {
                        v00 = fast_tanh(v00); v01 = fast_tanh(v01);
                        v10 = fast_tanh(v10); v11 = fast_tanh(v11);
                    }
                    if (args.mode == 4) {
                        *reinterpret_cast<__half2*>(args.Dh + (size_t)r0 * args.ldd + c0) =
                            __halves2half2(__float2half_rn(v00), __float2half_rn(v01));
                        *reinterpret_cast<__half2*>(args.Dh + (size_t)(r0 + 8) * args.ldd + c0) =
                            __halves2half2(__float2half_rn(v10), __float2half_rn(v11));
                    } else {
                        args.D[(size_t)r0 * args.ldd + c0] = v00;
                        args.D[(size_t)r0 * args.ldd + c0 + 1] = v01;
                        args.D[(size_t)(r0 + 8) * args.ldd + c0] = v10;
                        args.D[(size_t)(r0 + 8) * args.ldd + c0 + 1] = v11;
                    }
                }
            }
        }
    } else {
        if (set == 0) {
            const float* r = red + swid * 1024 + lane * 32;
            #pragma unroll
            for (int mt = 0; mt < 2; mt++) {
                int lr = wm * 32 + mt * 16 + (lane >> 2);
                #pragma unroll
                for (int nt = 0; nt < 4; nt++) {
                    int lc = wn * 32 + nt * 8 + (lane & 3) * 2;
                    float bia0 = args.bias[bn + lc];
                    float bia1 = args.bias[bn + lc + 1];
                    gsm[lr * 64 + lc]            = acc[mt][nt][0] + r[mt * 16 + nt * 4 + 0] + bia0;
                    gsm[lr * 64 + lc + 1]        = acc[mt][nt][1] + r[mt * 16 + nt * 4 + 1] + bia1;
                    gsm[(lr + 8) * 64 + lc]      = acc[mt][nt][2] + r[mt * 16 + nt * 4 + 2] + bia0;
                    gsm[(lr + 8) * 64 + lc + 1]  = acc[mt][nt][3] + r[mt * 16 + nt * 4 + 3] + bia1;
                }
            }
        }
        __syncthreads();
        #pragma unroll
        for (int it = 0; it < 4; it++) {
            int idx = tid + it * 256;
            int row = idx >> 4;
            int u = idx & 15;
            float4 gq = *reinterpret_cast<float4*>(&gsm[row * 64 + u * 4]);  // i,f,g,o
            int gr = bm + row;
            int ju = (bn >> 2) + u;
            size_t hix = (size_t)gr * HD + ju;
            float cn = fast_sigm(gq.y) * args.cellC[hix] + fast_sigm(gq.x) * fast_tanh(gq.z);
            float hn = fast_sigm(gq.w) * fast_tanh(cn);
            args.cellC[hix] = cn;
            __half hh = __float2half_rn(hn);
            args.cellHhi[hix] = hh;
            args.cellHlo[hix] = __float2half_rn(hn - __half2float(hh));
        }
    }
    __syncthreads();
}

// standalone wrapper (enc_proj, out-GEMM)
__global__ void __launch_bounds__(256)
gemm_f16s(GemmArgs3 args) {
    extern __shared__ char smem_raw[];
    gemm_tile(args, blockIdx.x, blockIdx.y, blockIdx.z, smem_raw);
}

// ---------------- attention phase (device fn, 256 threads, CTA = batch row) ----------------
__device__ void attn_phase(char* smem_raw, int b,
                           const float* __restrict__ corr_w,
                           const float* __restrict__ corr_b,
                           const int* __restrict__ mask,
                           const float* __restrict__ dhp_b) {
    const int tid = threadIdx.x;
    const int lane = tid & 31;
    const int warp = tid >> 5;     // 8 warps

    float* sm_q = (float*)smem_raw;        // 512
    float* sm_e = sm_q + AP;               // 128
    float* sm_a = sm_e + LL;               // 128

    for (int i = tid; i < AP; i += 256) {
        float s = dhp_b[i];
        #pragma unroll
        for (int z = 0; z < QSPLIT; z++)
            s += __ldcg(&g_qpart[(size_t)z * BB * AP + b * AP + i]);
        sm_q[i] = s;
    }
    __syncthreads();

    for (int l = warp; l < LL; l += 8) {
        const __half* ep = g_enc_projh + ((size_t)b * LL + l) * AP;
        float s = 0.0f;
        #pragma unroll
        for (int k = 0; k < 8; k++) {
            int ap = lane * 2 + k * 64;
            __half2 v = *reinterpret_cast<const __half2*>(ep + ap);
            s += tanh_mufu(__low2float(v) + sm_q[ap]) * corr_w[ap];
            s += tanh_mufu(__high2float(v) + sm_q[ap + 1]) * corr_w[ap + 1];
        }
        #pragma unroll
        for (int o = 16; o; o >>= 1) s += __shfl_down_sync(0xffffffffu, s, o);
        if (lane == 0) {
            float v = s + corr_b[0];
            if (mask[b * LL + l] != 0) v = -INFINITY;
            sm_e[l] = v;
        }
    }
    __syncthreads();

    if (warp == 0) {
        float m = -INFINITY;
        #pragma unroll
        for (int i = lane; i < LL; i += 32) m = fmaxf(m, sm_e[i]);
        #pragma unroll
        for (int o = 16; o; o >>= 1) m = fmaxf(m, __shfl_xor_sync(0xffffffffu, m, o));
        float sum = 0.0f;
        #pragma unroll
        for (int i = lane; i < LL; i += 32) sum += __expf(sm_e[i] - m);
        #pragma unroll
        for (int o = 16; o; o >>= 1) sum += __shfl_xor_sync(0xffffffffu, sum, o);
        float inv = __fdividef(1.0f, sum);
        #pragma unroll
        for (int i = lane; i < LL; i += 32) sm_a[i] = __expf(sm_e[i] - m) * inv;
    }
    __syncthreads();

    // context: 4 columns per thread (1024 = 256*4)
    {
        int h0 = tid * 4;
        const __half* eb = g_ench + (size_t)b * LL * HE + h0;
        float a0 = 0.0f, a1 = 0.0f, a2 = 0.0f, a3 = 0.0f;
        #pragma unroll 4
        for (int l = 0; l < LL; l++) {
            const __half2* p = reinterpret_cast<const __half2*>(eb + (size_t)l * HE);
            __half2 v0 = p[0], v1 = p[1];
            float al = sm_a[l];
            a0 = fmaf(al, __low2float(v0), a0);
            a1 = fmaf(al, __high2float(v0), a1);
            a2 = fmaf(al, __low2float(v1), a2);
            a3 = fmaf(al, __high2float(v1), a3);
        }
        __half b0 = __float2half_rn(a0), b1 = __float2half_rn(a1);
        __half b2 = __float2half_rn(a2), b3 = __float2half_rn(a3);
        __half2* dh = reinterpret_cast<__half2*>(g_athi + (size_t)b * HE + h0);
        dh[0] = __halves2half2(b0, b1);
        dh[1] = __halves2half2(b2, b3);
        __half2* dl = reinterpret_cast<__half2*>(g_atlo + (size_t)b * HE + h0);
        dl[0] = __halves2half2(__float2half_rn(a0 - __half2float(b0)),
                               __float2half_rn(a1 - __half2float(b1)));
        dl[1] = __halves2half2(__float2half_rn(a2 - __half2float(b2)),
                               __float2half_rn(a3 - __half2float(b3)));
    }
    __syncthreads();
}

// ---------------- persistent decoder loop: 128 CTAs x 256 threads ----------------
__global__ void __launch_bounds__(256)
decoder_loop(const float* __restrict__ corr_w, const float* __restrict__ corr_b,
             const int* __restrict__ mask, const float* __restrict__ dhp_b) {
    extern __shared__ char smem[];
    const int cta = blockIdx.x;

    for (int t = 0; t < TT; t++) {
        const int cur = t & 1, nxt = cur ^ 1;
        const __half* hp_hi = (t == 0) ? g_hp0hi : g_h2hi[cur];
        const __half* hp_lo = (t == 0) ? g_hp0lo : g_h2lo[cur];
        const __half* h1p_hi = (t == 0) ? g_h1inithi : g_h1ahi + (size_t)(t - 1) * BB * HD;
        const __half* h1p_lo = (t == 0) ? g_h1initlo : g_h1alo + (size_t)(t - 1) * BB * HD;
        __half* h1c_hi = g_h1ahi + (size_t)t * BB * HD;
        __half* h1c_lo = g_h1alo + (size_t)t * BB * HD;

        // phase 1: q partials (16 tile positions x 8 split-K) = 128 CTAs, apass=1
        {
            GemmArgs3 a = {};
            a.seg[0] = {hp_hi, hp_lo, HD, g_wh + O_DHPW, AP, HD};
            a.nseg = 1; a.apass = 1; a.D = g_qpart; a.ldd = AP; a.bias = nullptr; a.mode = 0;
            a.zchunk = HD / QSPLIT;
            int z = cta >> 4, rem = cta & 15;
            gemm_tile(a, rem & 7, rem >> 3, z, smem);
        }
        grid_sync();

        // phase 2: attention (CTA = batch row)
        attn_phase(smem, cta, corr_w, corr_b, mask, dhp_b);
        grid_sync();

        // phase 3: gates1 + cell1 (64 x 2 = 128 tiles), apass=2
        {
            GemmArgs3 a = {};
            a.seg[0] = {g_caphi + (size_t)t * BB * EE, g_caplo + (size_t)t * BB * EE, EE,
                        g_wh + O_IH1, G4, EE};
            a.seg[1] = {g_athi, g_atlo, HE, g_wh + O_IH1 + (size_t)EE * G4, G4, HE};
            a.seg[2] = {h1p_hi, h1p_lo, HD, g_wh + O_HH1, G4, HD};
            a.nseg = 3; a.apass = 2; a.bias = g_b1p; a.mode = 2; a.zchunk = 0;
            a.cellC = g_c1; a.cellHhi = h1c_hi; a.cellHlo = h1c_lo;
            gemm_tile(a, cta & 63, cta >> 6, 0, smem);
        }
        grid_sync();

        // phase 4: gates2 + cell2 (64 x 2 = 128 tiles), apass=2
        {
            GemmArgs3 a = {};
            a.seg[0] = {h1c_hi, h1c_lo, HD, g_wh + O_IH2, G4, HD};
            a.seg[1] = {g_h2hi[cur], g_h2lo[cur], HD, g_wh + O_HH2, G4, HD};
            a.nseg = 2; a.apass = 2; a.bias = g_b2p; a.mode = 2; a.zchunk = 0;
            a.cellC = g_c2; a.cellHhi = g_h2hi[nxt]; a.cellHlo = g_h2lo[nxt];
            gemm_tile(a, cta & 63, cta >> 6, 0, smem);
        }
        grid_sync();
    }
}

// ---------------- launch ----------------
extern "C" void kernel_launch(void* const* d_in, const int* in_sizes, int n_in,
                              void* d_out, int out_size) {
    const float* enc      = (const float*)d_in[0];
    const int*   mask     = (const int*)  d_in[1];
    const float* h1_0     = (const float*)d_in[2];
    const float* c1_0     = (const float*)d_in[3];
    const float* h2_0     = (const float*)d_in[4];
    const float* c2_0     = (const float*)d_in[5];
    const float* captions = (const float*)d_in[6];
    const float* att_W    = (const float*)d_in[7];
    const float* att_b    = (const float*)d_in[8];
    const float* dhp_W    = (const float*)d_in[9];
    const float* dhp_b    = (const float*)d_in[10];
    const float* corr_w   = (const float*)d_in[11];
    const float* corr_b   = (const float*)d_in[12];
    const float* lt_W     = (const float*)d_in[13];
    const float* lt_b     = (const float*)d_in[14];
    const float* W_ih1    = (const float*)d_in[15];
    const float* W_hh1    = (const float*)d_in[16];
    const float* b_ih1    = (const float*)d_in[17];
    const float* b_hh1    = (const float*)d_in[18];
    const float* W_ih2    = (const float*)d_in[19];
    const float* W_hh2    = (const float*)d_in[20];
    const float* b_ih2    = (const float*)d_in[21];
    const float* b_hh2    = (const float*)d_in[22];
    float* out = (float*)d_out;

    cudaFuncSetAttribute(gemm_f16s, cudaFuncAttributeMaxDynamicSharedMemorySize, SMEM_BYTES);
    cudaFuncSetAttribute(decoder_loop, cudaFuncAttributeMaxDynamicSharedMemorySize, SMEM_BYTES);

    __half *p_encprojh, *p_wh, *p_ench, *p_caphi, *p_caplo, *p_h1ahi, *p_h1alo;
    cudaGetSymbolAddress((void**)&p_encprojh, g_enc_projh);
    cudaGetSymbolAddress((void**)&p_wh,    g_wh);
    cudaGetSymbolAddress((void**)&p_ench,  g_ench);
    cudaGetSymbolAddress((void**)&p_caphi, g_caphi);
    cudaGetSymbolAddress((void**)&p_caplo, g_caplo);
    cudaGetSymbolAddress((void**)&p_h1ahi, g_h1ahi);
    cudaGetSymbolAddress((void**)&p_h1alo, g_h1alo);

    // ---- prep ----
    f32_cvt4<<<(HE * AP / 4 + 255) / 256, 256>>>(
        (const float4*)att_W, (__half2*)(p_wh + O_ATTW), HE * AP / 4);
    f32_cvt4<<<(HD * AP / 4 + 255) / 256, 256>>>(
        (const float4*)dhp_W, (__half2*)(p_wh + O_DHPW), HD * AP / 4);
    f32_cvt4<<<(HD * HD / 4 + 255) / 256, 256>>>(
        (const float4*)lt_W, (__half2*)(p_wh + O_LTW), HD * HD / 4);
    f32_cvt4<<<(BB * LL * HE / 4 + 255) / 256, 256>>>(
        (const float4*)enc, (__half2*)p_ench, BB * LL * HE / 4);
    f32_split4<<<(TT * BB * EE / 4 + 255) / 256, 256>>>(
        (const float4*)captions, (__half2*)p_caphi, (__half2*)p_caplo, TT * BB * EE / 4);
    f32_cvt_perm<<<((EE + HE) * G4 + 255) / 256, 256>>>(W_ih1, p_wh + O_IH1, EE + HE);
    f32_cvt_perm<<<(HD * G4 + 255) / 256, 256>>>(W_hh1, p_wh + O_HH1, HD);
    f32_cvt_perm<<<(HD * G4 + 255) / 256, 256>>>(W_ih2, p_wh + O_IH2, HD);
    f32_cvt_perm<<<(HD * G4 + 255) / 256, 256>>>(W_hh2, p_wh + O_HH2, HD);
    bias_prep<<<(G4 + 255) / 256, 256>>>(b_ih1, b_hh1, b_ih2, b_hh2);
    init_state<<<(BB * HD + 255) / 256, 256>>>(h1_0, c1_0, h2_0, c2_0);

    // enc_proj = enc @ att_W + att_b (fp16 out, apass=1)
    {
        GemmArgs3 a = {};
        a.seg[0] = {p_ench, p_ench, HE, p_wh + O_ATTW, AP, HE};
        a.nseg = 1; a.apass = 1; a.ldd = AP; a.bias = att_b; a.mode = 4;
        a.Dh = p_encprojh; a.zchunk = 0;
        gemm_f16s<<<dim3(AP / 64, (BB * LL) / 64), 256, SMEM_BYTES>>>(a);
    }

    // full 64-step decoder loop: ONE persistent kernel
    decoder_loop<<<NCTA, 256, SMEM_BYTES>>>(corr_w, corr_b, mask, dhp_b);

    // final batched out-projection: out = tanh(h1_archive @ lt_W + lt_b), apass=1 (leaf)
    {
        GemmArgs3 a = {};
        a.seg[0] = {p_h1ahi, p_h1alo, HD, p_wh + O_LTW, HD, HD};
        a.nseg = 1; a.apass = 1; a.D = out; a.ldd = HD; a.bias = lt_b; a.mode = 1; a.zchunk = 0;
        gemm_f16s<<<dim3(HD / 64, (TT * BB) / 64), 256, SMEM_BYTES>>>(a);
    }

    (void)in_sizes; (void)n_in; (void)out_size;
}

// round 14
// speedup vs baseline: 1.1264x; 1.0034x over previous
#include <cuda_runtime.h>
#include <cuda_fp16.h>
#include <math.h>
#include <stdint.h>

// Problem constants
#define BB 128   // batch
#define LL 128   // enc length
#define HE 1024  // enc hidden
#define HD 1024  // dec hidden
#define EE 512   // embed
#define AP 512   // attn proj
#define TT 64    // timesteps
#define G4 (4*HD)
#define QSPLIT 8
#define NCTA 128

// ---------------- device scratch ----------------
__device__ __half g_enc_projh[BB * LL * AP];   // fp16 enc_proj (read-only in loop)
__device__ float g_qpart[QSPLIT * BB * AP];
__device__ float g_c1[BB * HD];
__device__ float g_c2[BB * HD];
__device__ float g_b1p[G4];
__device__ float g_b2p[G4];

__device__ __half g_h1ahi[TT * BB * HD], g_h1alo[TT * BB * HD];   // h1 archive
__device__ __half g_h1inithi[BB * HD], g_h1initlo[BB * HD];
__device__ __half g_h2hi[2][BB * HD], g_h2lo[2][BB * HD];
__device__ __half g_hp0hi[BB * HD], g_hp0lo[BB * HD];
__device__ __half g_athi[BB * HE], g_atlo[BB * HE];
__device__ __half g_caphi[TT * BB * EE], g_caplo[TT * BB * EE];
__device__ __half g_ench[BB * LL * HE];

#define WPOOL 20971520
__device__ __half g_wh[WPOOL];

// weight pool offsets (compile-time)
#define O_ATTW ((size_t)0)
#define O_DHPW (O_ATTW + (size_t)HE * AP)
#define O_IH1  (O_DHPW + (size_t)HD * AP)
#define O_HH1  (O_IH1  + (size_t)(EE + HE) * G4)
#define O_IH2  (O_HH1  + (size_t)HD * G4)
#define O_HH2  (O_IH2  + (size_t)HD * G4)
#define O_LTW  (O_HH2  + (size_t)HD * G4)

// software grid barrier
__device__ unsigned g_bar_count = 0;
__device__ volatile unsigned g_bar_gen = 0;

__device__ __forceinline__ void grid_sync() {
    __threadfence();
    __syncthreads();
    if (threadIdx.x == 0) {
        unsigned gen = g_bar_gen;
        if (atomicAdd(&g_bar_count, 1u) == NCTA - 1u) {
            g_bar_count = 0;
            __threadfence();
            g_bar_gen = gen + 1;
        } else {
            while (g_bar_gen == gen) __nanosleep(32);
        }
    }
    __syncthreads();
}

__device__ __forceinline__ float fast_tanh(float x) {
    float e = __expf(2.0f * x);
    return 1.0f - __fdividef(2.0f, e + 1.0f);
}
__device__ __forceinline__ float fast_sigm(float x) {
    return __fdividef(1.0f, 1.0f + __expf(-x));
}
__device__ __forceinline__ float tanh_mufu(float x) {
    float y;
    asm("tanh.approx.f32 %0, %1;" : "=f"(y) : "f"(x));
    return y;
}

// ---------------- prep kernels ----------------
__global__ void init_state(const float* __restrict__ h1_0, const float* __restrict__ c1_0,
                           const float* __restrict__ h2_0, const float* __restrict__ c2_0) {
    int i = blockIdx.x * blockDim.x + threadIdx.x;
    if (i < BB * HD) {
        float h1 = h1_0[i], h2 = h2_0[i];
        __half a = __float2half_rn(h1);
        g_h1inithi[i] = a; g_h1initlo[i] = __float2half_rn(h1 - __half2float(a));
        __half b = __float2half_rn(h2);
        g_h2hi[0][i] = b; g_h2lo[0][i] = __float2half_rn(h2 - __half2float(b));
        g_c1[i] = c1_0[i];
        g_c2[i] = c2_0[i];
        g_hp0hi[i] = __float2half_rn(1.0f / (float)HE);
        g_hp0lo[i] = __float2half_rn(0.0f);
    }
}

__global__ void f32_split4(const float4* __restrict__ src,
                           __half2* __restrict__ hi,
                           __half2* __restrict__ lo, int n4) {
    int i = blockIdx.x * 256 + threadIdx.x;
    if (i < n4) {
        float4 v = src[i];
        __half h0 = __float2half_rn(v.x);
        __half h1 = __float2half_rn(v.y);
        __half h2 = __float2half_rn(v.z);
        __half h3 = __float2half_rn(v.w);
        hi[2 * i]     = __halves2half2(h0, h1);
        hi[2 * i + 1] = __halves2half2(h2, h3);
        lo[2 * i]     = __halves2half2(
            __float2half_rn(v.x - __half2float(h0)),
            __float2half_rn(v.y - __half2float(h1)));
        lo[2 * i + 1] = __halves2half2(
            __float2half_rn(v.z - __half2float(h2)),
            __float2half_rn(v.w - __half2float(h3)));
    }
}

__global__ void f32_cvt4(const float4* __restrict__ src, __half2* __restrict__ dst, int n4) {
    int i = blockIdx.x * 256 + threadIdx.x;
    if (i < n4) {
        float4 v = src[i];
        dst[2 * i]     = __halves2half2(__float2half_rn(v.x), __float2half_rn(v.y));
        dst[2 * i + 1] = __halves2half2(__float2half_rn(v.z), __float2half_rn(v.w));
    }
}

__global__ void f32_cvt_perm(const float* __restrict__ src, __half* __restrict__ dst, int K) {
    int i = blockIdx.x * 256 + threadIdx.x;
    if (i < K * G4) {
        int row = i / G4, cd = i % G4;
        int j = cd >> 2, gate = cd & 3;
        dst[i] = __float2half_rn(src[(size_t)row * G4 + gate * HD + j]);
    }
}

__global__ void bias_prep(const float* __restrict__ bi1, const float* __restrict__ bh1,
                          const float* __restrict__ bi2, const float* __restrict__ bh2) {
    int i = blockIdx.x * 256 + threadIdx.x;
    if (i < G4) {
        int j = i >> 2, gate = i & 3;
        g_b1p[i] = bi1[gate * HD + j] + bh1[gate * HD + j];
        g_b2p[i] = bi2[gate * HD + j] + bh2[gate * HD + j];
    }
}

// ---------------- fp16 split-A tensor-core GEMM tile (template on APASS) ----------------
struct Seg2 {
    const __half* Ahi; const __half* Alo; int lda;
    const __half* B; int ldb;
    int K;
};
struct GemmArgs3 {
    Seg2 seg[3];
    int nseg;
    float* D; int ldd;
    const float* bias;
    int mode;                 // 0 plain f32, 1 tanh f32, 2 cell, 4 fp16 out
    float* cellC; __half* cellHhi; __half* cellHlo;
    __half* Dh;
    int zchunk;
};

#define PADA 40
#define PADB 72
#define STG 3
#define A_SET_H (STG * 64 * PADA)
#define B_SET_H (STG * 32 * PADB)
#define SET_H   (2 * A_SET_H + B_SET_H)
#define SMEM_BYTES (2 * SET_H * 2)

__device__ __forceinline__ uint32_t smem_u32(const void* p) {
    return (uint32_t)__cvta_generic_to_shared(p);
}
// cg: bypass L1 (persistent kernel; cross-CTA producer/consumer)
__device__ __forceinline__ void cp16(void* dst, const void* src) {
    asm volatile("cp.async.cg.shared.global [%0], [%1], 16;"
                 :: "r"(smem_u32(dst)), "l"(src));
}
__device__ __forceinline__ void ldsm_x4(uint32_t addr, uint32_t* r) {
    asm volatile("ldmatrix.sync.aligned.m8n8.x4.shared.b16 {%0,%1,%2,%3}, [%4];"
                 : "=r"(r[0]), "=r"(r[1]), "=r"(r[2]), "=r"(r[3]) : "r"(addr));
}
__device__ __forceinline__ void ldsm_x4_t(uint32_t addr, uint32_t& r0, uint32_t& r1,
                                          uint32_t& r2, uint32_t& r3) {
    asm volatile("ldmatrix.sync.aligned.m8n8.x4.trans.shared.b16 {%0,%1,%2,%3}, [%4];"
                 : "=r"(r0), "=r"(r1), "=r"(r2), "=r"(r3) : "r"(addr));
}
__device__ __forceinline__ void mma16816(float* c, const uint32_t* a, const uint32_t* b) {
    asm volatile(
        "mma.sync.aligned.m16n8k16.row.col.f32.f16.f16.f32 "
        "{%0,%1,%2,%3}, {%4,%5,%6,%7}, {%8,%9}, {%0,%1,%2,%3};"
        : "+f"(c[0]), "+f"(c[1]), "+f"(c[2]), "+f"(c[3])
        : "r"(a[0]), "r"(a[1]), "r"(a[2]), "r"(a[3]), "r"(b[0]), "r"(b[1]));
}
__device__ __forceinline__ void bar_set(int set) {
    asm volatile("bar.sync %0, 128;" :: "r"(set + 1) : "memory");
}

template <int APASS>
__device__ __forceinline__ void stage_tile(const GemmArgs3& a, int g, int bm, int bn, int stid,
                                           __half* AsH, __half* AsL, __half* Bs) {
    int s = 0, rem = g;
    #pragma unroll
    for (int i = 0; i < 2; i++)
        if (s < a.nseg - 1 && rem >= (a.seg[s].K >> 5)) { rem -= a.seg[s].K >> 5; s++; }
    const Seg2 sg = a.seg[s];
    const int k0 = rem << 5;
    #pragma unroll
    for (int i = 0; i < 2; i++) {
        int ch = stid + i * 128;
        int row = ch >> 2, c = (ch & 3) * 8;
        size_t off = (size_t)(bm + row) * sg.lda + k0 + c;
        cp16(AsH + row * PADA + c, sg.Ahi + off);
        if (APASS == 2) cp16(AsL + row * PADA + c, sg.Alo + off);
    }
    #pragma unroll
    for (int i = 0; i < 2; i++) {
        int ch = stid + i * 128;
        int row = ch >> 3, c = (ch & 7) * 8;
        size_t off = (size_t)(k0 + row) * sg.ldb + bn + c;
        cp16(Bs + row * PADB + c, sg.B + off);
    }
}

template <int APASS>
__device__ void gemm_tile(GemmArgs3 args, int bx, int by, int bz, char* smem_raw) {
    __half* base = (__half*)smem_raw;

    if (args.zchunk > 0) {
        args.seg[0].Ahi += (size_t)bz * args.zchunk;
        args.seg[0].Alo += (size_t)bz * args.zchunk;
        args.seg[0].B   += (size_t)bz * args.zchunk * args.seg[0].ldb;
        args.seg[0].K = args.zchunk;
        args.D += (size_t)bz * BB * args.ldd;
    }

    const int tid = threadIdx.x;
    const int lane = tid & 31;
    const int wid = tid >> 5;
    const int set = wid >> 2;
    const int swid = wid & 3;
    const int stid = tid & 127;
    const int wm = swid & 1;
    const int wn = swid >> 1;
    const int bm = by * 64;
    const int bn = bx * 64;

    __half* AsH = base + set * SET_H;
    __half* AsL = AsH + A_SET_H;
    __half* Bs  = AsL + A_SET_H;
    float* red = (float*)(base + SET_H);
    float* gsm = (float*)base;

    int ntile = 0;
    #pragma unroll
    for (int s = 0; s < 3; s++) if (s < args.nseg) ntile += args.seg[s].K >> 5;
    const int cnt = (ntile - set + 1) >> 1;

    float acc[2][4][4];
    #pragma unroll
    for (int i = 0; i < 2; i++)
        #pragma unroll
        for (int j = 0; j < 4; j++)
            #pragma unroll
            for (int k = 0; k < 4; k++) acc[i][j][k] = 0.0f;

    const int a_r = lane & 15;
    const int a_c = (lane >> 4) << 3;
    const int b_r = (lane & 7) + ((lane >> 3) & 1) * 8;
    const int b_c = (lane >> 4) << 3;

    if (cnt > 0)
        stage_tile<APASS>(args, set, bm, bn, stid, AsH, AsL, Bs);
    asm volatile("cp.async.commit_group;");
    if (cnt > 1)
        stage_tile<APASS>(args, 2 + set, bm, bn, stid,
                          AsH + 64 * PADA, AsL + 64 * PADA, Bs + 32 * PADB);
    asm volatile("cp.async.commit_group;");

    for (int j = 0; j < cnt; j++) {
        asm volatile("cp.async.wait_group 1;");
        bar_set(set);
        {
            int p = (j + 2) % 3;
            if (j + 2 < cnt)
                stage_tile<APASS>(args, 2 * (j + 2) + set, bm, bn, stid,
                                  AsH + p * 64 * PADA, AsL + p * 64 * PADA, Bs + p * 32 * PADB);
            asm volatile("cp.async.commit_group;");
        }
        const int q = j % 3;
        const __half* cAH = AsH + q * 64 * PADA;
        const __half* cAL = AsL + q * 64 * PADA;
        const __half* cB  = Bs + q * 32 * PADB;
        #pragma unroll
        for (int kk = 0; kk < 32; kk += 16) {
            uint32_t ah[2][4], al[2][4];
            #pragma unroll
            for (int mt = 0; mt < 2; mt++) {
                int rowoff = (wm * 32 + mt * 16 + a_r) * PADA + kk + a_c;
                ldsm_x4(smem_u32(&cAH[rowoff]), ah[mt]);
                if (APASS == 2) ldsm_x4(smem_u32(&cAL[rowoff]), al[mt]);
            }
            uint32_t bh[4][2];
            #pragma unroll
            for (int gi = 0; gi < 2; gi++) {
                int boff = (kk + b_r) * PADB + wn * 32 + gi * 16 + b_c;
                ldsm_x4_t(smem_u32(&cB[boff]),
                          bh[gi * 2][0], bh[gi * 2][1], bh[gi * 2 + 1][0], bh[gi * 2 + 1][1]);
            }
            #pragma unroll
            for (int mt = 0; mt < 2; mt++)
                #pragma unroll
                for (int nt = 0; nt < 4; nt++) {
                    mma16816(acc[mt][nt], ah[mt], bh[nt]);
                    if (APASS == 2) mma16816(acc[mt][nt], al[mt], bh[nt]);
                }
        }
    }

    asm volatile("cp.async.wait_group 0;");
    __syncthreads();

    if (set == 1) {
        float* r = red + swid * 1024 + lane * 32;
        #pragma unroll
        for (int mt = 0; mt < 2; mt++)
            #pragma unroll
            for (int nt = 0; nt < 4; nt++)
                #pragma unroll
                for (int k = 0; k < 4; k++)
                    r[mt * 16 + nt * 4 + k] = acc[mt][nt][k];
    }
    __syncthreads();

    if (args.mode != 2) {
        if (set == 0) {
            const float* r = red + swid * 1024 + lane * 32;
            const int do_tanh = (args.mode == 1);
            #pragma unroll
            for (int mt = 0; mt < 2; mt++) {
                int r0 = bm + wm * 32 + mt * 16 + (lane >> 2);
                #pragma unroll
                for (int nt = 0; nt < 4; nt++) {
                    int c0 = bn + wn * 32 + nt * 8 + (lane & 3) * 2;
                    float bia0 = 0.0f, bia1 = 0.0f;
                    if (args.bias) { bia0 = args.bias[c0]; bia1 = args.bias[c0 + 1]; }
                    float v00 = acc[mt][nt][0] + r[mt * 16 + nt * 4 + 0] + bia0;
                    float v01 = acc[mt][nt][1] + r[mt * 16 + nt * 4 + 1] + bia1;
                    float v10 = acc[mt][nt][2] + r[mt * 16 + nt * 4 + 2] + bia0;
                    float v11 = acc[mt][nt][3] + r[mt * 16 + nt * 4 + 3] + bia1;
                    if (do_tanh) {
                        v00 = fast_tanh(v00); v01 = fast_tanh(v01);
                        v10 = fast_tanh(v10); v11 = fast_tanh(v11);
                    }
                    if (args.mode == 4) {
                        *reinterpret_cast<__half2*>(args.Dh + (size_t)r0 * args.ldd + c0) =
                            __halves2half2(__float2half_rn(v00), __float2half_rn(v01));
                        *reinterpret_cast<__half2*>(args.Dh + (size_t)(r0 + 8) * args.ldd + c0) =
                            __halves2half2(__float2half_rn(v10), __float2half_rn(v11));
                    } else {
                        args.D[(size_t)r0 * args.ldd + c0] = v00;
                        args.D[(size_t)r0 * args.ldd + c0 + 1] = v01;
                        args.D[(size_t)(r0 + 8) * args.ldd + c0] = v10;
                        args.D[(size_t)(r0 + 8) * args.ldd + c0 + 1] = v11;
                    }
                }
            }
        }
    } else {
        if (set == 0) {
            const float* r = red + swid * 1024 + lane * 32;
            #pragma unroll
            for (int mt = 0; mt < 2; mt++) {
                int lr = wm * 32 + mt * 16 + (lane >> 2);
                #pragma unroll
                for (int nt = 0; nt < 4; nt++) {
                    int lc = wn * 32 + nt * 8 + (lane & 3) * 2;
                    float bia0 = args.bias[bn + lc];
                    float bia1 = args.bias[bn + lc + 1];
                    gsm[lr * 64 + lc]            = acc[mt][nt][0] + r[mt * 16 + nt * 4 + 0] + bia0;
                    gsm[lr * 64 + lc + 1]        = acc[mt][nt][1] + r[mt * 16 + nt * 4 + 1] + bia1;
                    gsm[(lr + 8) * 64 + lc]      = acc[mt][nt][2] + r[mt * 16 + nt * 4 + 2] + bia0;
                    gsm[(lr + 8) * 64 + lc + 1]  = acc[mt][nt][3] + r[mt * 16 + nt * 4 + 3] + bia1;
                }
            }
        }
        __syncthreads();
        #pragma unroll
        for (int it = 0; it < 4; it++) {
            int idx = tid + it * 256;
            int row = idx >> 4;
            int u = idx & 15;
            float4 gq = *reinterpret_cast<float4*>(&gsm[row * 64 + u * 4]);  // i,f,g,o
            int gr = bm + row;
            int ju = (bn >> 2) + u;
            size_t hix = (size_t)gr * HD + ju;
            float cn = fast_sigm(gq.y) * args.cellC[hix] + fast_sigm(gq.x) * fast_tanh(gq.z);
            float hn = fast_sigm(gq.w) * fast_tanh(cn);
            args.cellC[hix] = cn;
            __half hh = __float2half_rn(hn);
            args.cellHhi[hix] = hh;
            args.cellHlo[hix] = __float2half_rn(hn - __half2float(hh));
        }
    }
    __syncthreads();
}

// standalone wrappers (enc_proj, out-GEMM)
template <int APASS>
__global__ void __launch_bounds__(256)
gemm_f16s(GemmArgs3 args) {
    extern __shared__ char smem_raw[];
    gemm_tile<APASS>(args, blockIdx.x, blockIdx.y, blockIdx.z, smem_raw);
}

// ---------------- attention phase (device fn, 256 threads, CTA = batch row) ----------------
__device__ void attn_phase(char* smem_raw, int b,
                           const float* __restrict__ corr_w,
                           const float* __restrict__ corr_b,
                           const int* __restrict__ mask,
                           const float* __restrict__ dhp_b) {
    const int tid = threadIdx.x;
    const int lane = tid & 31;
    const int warp = tid >> 5;     // 8 warps

    float* sm_q = (float*)smem_raw;
    float* sm_e = sm_q + AP;
    float* sm_a = sm_e + LL;

    for (int i = tid; i < AP; i += 256) {
        float s = dhp_b[i];
        #pragma unroll
        for (int z = 0; z < QSPLIT; z++)
            s += __ldcg(&g_qpart[(size_t)z * BB * AP + b * AP + i]);
        sm_q[i] = s;
    }
    __syncthreads();

    for (int l = warp; l < LL; l += 8) {
        const __half* ep = g_enc_projh + ((size_t)b * LL + l) * AP;
        float s = 0.0f;
        #pragma unroll
        for (int k = 0; k < 8; k++) {
            int ap = lane * 2 + k * 64;
            __half2 v = *reinterpret_cast<const __half2*>(ep + ap);
            s += tanh_mufu(__low2float(v) + sm_q[ap]) * corr_w[ap];
            s += tanh_mufu(__high2float(v) + sm_q[ap + 1]) * corr_w[ap + 1];
        }
        #pragma unroll
        for (int o = 16; o; o >>= 1) s += __shfl_down_sync(0xffffffffu, s, o);
        if (lane == 0) {
            float v = s + corr_b[0];
            if (mask[b * LL + l] != 0) v = -INFINITY;
            sm_e[l] = v;
        }
    }
    __syncthreads();

    if (warp == 0) {
        float m = -INFINITY;
        #pragma unroll
        for (int i = lane; i < LL; i += 32) m = fmaxf(m, sm_e[i]);
        #pragma unroll
        for (int o = 16; o; o >>= 1) m = fmaxf(m, __shfl_xor_sync(0xffffffffu, m, o));
        float sum = 0.0f;
        #pragma unroll
        for (int i = lane; i < LL; i += 32) sum += __expf(sm_e[i] - m);
        #pragma unroll
        for (int o = 16; o; o >>= 1) sum += __shfl_xor_sync(0xffffffffu, sum, o);
        float inv = __fdividef(1.0f, sum);
        #pragma unroll
        for (int i = lane; i < LL; i += 32) sm_a[i] = __expf(sm_e[i] - m) * inv;
    }
    __syncthreads();

    // context: 4 columns per thread
    {
        int h0 = tid * 4;
        const __half* eb = g_ench + (size_t)b * LL * HE + h0;
        float a0 = 0.0f, a1 = 0.0f, a2 = 0.0f, a3 = 0.0f;
        #pragma unroll 4
        for (int l = 0; l < LL; l++) {
            const __half2* p = reinterpret_cast<const __half2*>(eb + (size_t)l * HE);
            __half2 v0 = p[0], v1 = p[1];
            float al = sm_a[l];
            a0 = fmaf(al, __low2float(v0), a0);
            a1 = fmaf(al, __high2float(v0), a1);
            a2 = fmaf(al, __low2float(v1), a2);
            a3 = fmaf(al, __high2float(v1), a3);
        }
        __half b0 = __float2half_rn(a0), b1 = __float2half_rn(a1);
        __half b2 = __float2half_rn(a2), b3 = __float2half_rn(a3);
        __half2* dh = reinterpret_cast<__half2*>(g_athi + (size_t)b * HE + h0);
        dh[0] = __halves2half2(b0, b1);
        dh[1] = __halves2half2(b2, b3);
        __half2* dl = reinterpret_cast<__half2*>(g_atlo + (size_t)b * HE + h0);
        dl[0] = __halves2half2(__float2half_rn(a0 - __half2float(b0)),
                               __float2half_rn(a1 - __half2float(b1)));
        dl[1] = __halves2half2(__float2half_rn(a2 - __half2float(b2)),
                               __float2half_rn(a3 - __half2float(b3)));
    }
    __syncthreads();
}

// ---------------- persistent decoder loop: 128 CTAs x 256 threads ----------------
__global__ void __launch_bounds__(256)
decoder_loop(const float* __restrict__ corr_w, const float* __restrict__ corr_b,
             const int* __restrict__ mask, const float* __restrict__ dhp_b) {
    extern __shared__ char smem[];
    const int cta = blockIdx.x;

    for (int t = 0; t < TT; t++) {
        const int cur = t & 1, nxt = cur ^ 1;
        const __half* hp_hi = (t == 0) ? g_hp0hi : g_h2hi[cur];
        const __half* hp_lo = (t == 0) ? g_hp0lo : g_h2lo[cur];
        const __half* h1p_hi = (t == 0) ? g_h1inithi : g_h1ahi + (size_t)(t - 1) * BB * HD;
        const __half* h1p_lo = (t == 0) ? g_h1initlo : g_h1alo + (size_t)(t - 1) * BB * HD;
        __half* h1c_hi = g_h1ahi + (size_t)t * BB * HD;
        __half* h1c_lo = g_h1alo + (size_t)t * BB * HD;

        // phase 1: q partials (16 tiles x 8 split-K), APASS=1 (scores tolerant)
        {
            GemmArgs3 a = {};
            a.seg[0] = {hp_hi, hp_lo, HD, g_wh + O_DHPW, AP, HD};
            a.nseg = 1; a.D = g_qpart; a.ldd = AP; a.bias = nullptr; a.mode = 0;
            a.zchunk = HD / QSPLIT;
            int z = cta >> 4, rem = cta & 15;
            gemm_tile<1>(a, rem & 7, rem >> 3, z, smem);
        }
        grid_sync();

        // phase 2: attention (CTA = batch row)
        attn_phase(smem, cta, corr_w, corr_b, mask, dhp_b);
        grid_sync();

        // phase 3: gates1 + cell1, APASS=2
        {
            GemmArgs3 a = {};
            a.seg[0] = {g_caphi + (size_t)t * BB * EE, g_caplo + (size_t)t * BB * EE, EE,
                        g_wh + O_IH1, G4, EE};
            a.seg[1] = {g_athi, g_atlo, HE, g_wh + O_IH1 + (size_t)EE * G4, G4, HE};
            a.seg[2] = {h1p_hi, h1p_lo, HD, g_wh + O_HH1, G4, HD};
            a.nseg = 3; a.bias = g_b1p; a.mode = 2; a.zchunk = 0;
            a.cellC = g_c1; a.cellHhi = h1c_hi; a.cellHlo = h1c_lo;
            gemm_tile<2>(a, cta & 63, cta >> 6, 0, smem);
        }
        grid_sync();

        // phase 4: gates2 + cell2, APASS=2
        {
            GemmArgs3 a = {};
            a.seg[0] = {h1c_hi, h1c_lo, HD, g_wh + O_IH2, G4, HD};
            a.seg[1] = {g_h2hi[cur], g_h2lo[cur], HD, g_wh + O_HH2, G4, HD};
            a.nseg = 2; a.bias = g_b2p; a.mode = 2; a.zchunk = 0;
            a.cellC = g_c2; a.cellHhi = g_h2hi[nxt]; a.cellHlo = g_h2lo[nxt];
            gemm_tile<2>(a, cta & 63, cta >> 6, 0, smem);
        }
        grid_sync();
    }
}

// ---------------- launch ----------------
extern "C" void kernel_launch(void* const* d_in, const int* in_sizes, int n_in,
                              void* d_out, int out_size) {
    const float* enc      = (const float*)d_in[0];
    const int*   mask     = (const int*)  d_in[1];
    const float* h1_0     = (const float*)d_in[2];
    const float* c1_0     = (const float*)d_in[3];
    const float* h2_0     = (const float*)d_in[4];
    const float* c2_0     = (const float*)d_in[5];
    const float* captions = (const float*)d_in[6];
    const float* att_W    = (const float*)d_in[7];
    const float* att_b    = (const float*)d_in[8];
    const float* dhp_W    = (const float*)d_in[9];
    const float* dhp_b    = (const float*)d_in[10];
    const float* corr_w   = (const float*)d_in[11];
    const float* corr_b   = (const float*)d_in[12];
    const float* lt_W     = (const float*)d_in[13];
    const float* lt_b     = (const float*)d_in[14];
    const float* W_ih1    = (const float*)d_in[15];
    const float* W_hh1    = (const float*)d_in[16];
    const float* b_ih1    = (const float*)d_in[17];
    const float* b_hh1    = (const float*)d_in[18];
    const float* W_ih2    = (const float*)d_in[19];
    const float* W_hh2    = (const float*)d_in[20];
    const float* b_ih2    = (const float*)d_in[21];
    const float* b_hh2    = (const float*)d_in[22];
    float* out = (float*)d_out;

    cudaFuncSetAttribute(gemm_f16s<1>, cudaFuncAttributeMaxDynamicSharedMemorySize, SMEM_BYTES);
    cudaFuncSetAttribute(gemm_f16s<2>, cudaFuncAttributeMaxDynamicSharedMemorySize, SMEM_BYTES);
    cudaFuncSetAttribute(decoder_loop, cudaFuncAttributeMaxDynamicSharedMemorySize, SMEM_BYTES);

    __half *p_encprojh, *p_wh, *p_ench, *p_caphi, *p_caplo, *p_h1ahi, *p_h1alo;
    cudaGetSymbolAddress((void**)&p_encprojh, g_enc_projh);
    cudaGetSymbolAddress((void**)&p_wh,    g_wh);
    cudaGetSymbolAddress((void**)&p_ench,  g_ench);
    cudaGetSymbolAddress((void**)&p_caphi, g_caphi);
    cudaGetSymbolAddress((void**)&p_caplo, g_caplo);
    cudaGetSymbolAddress((void**)&p_h1ahi, g_h1ahi);
    cudaGetSymbolAddress((void**)&p_h1alo, g_h1alo);

    // ---- prep ----
    f32_cvt4<<<(HE * AP / 4 + 255) / 256, 256>>>(
        (const float4*)att_W, (__half2*)(p_wh + O_ATTW), HE * AP / 4);
    f32_cvt4<<<(HD * AP / 4 + 255) / 256, 256>>>(
        (const float4*)dhp_W, (__half2*)(p_wh + O_DHPW), HD * AP / 4);
    f32_cvt4<<<(HD * HD / 4 + 255) / 256, 256>>>(
        (const float4*)lt_W, (__half2*)(p_wh + O_LTW), HD * HD / 4);
    f32_cvt4<<<(BB * LL * HE / 4 + 255) / 256, 256>>>(
        (const float4*)enc, (__half2*)p_ench, BB * LL * HE / 4);
    f32_split4<<<(TT * BB * EE / 4 + 255) / 256, 256>>>(
        (const float4*)captions, (__half2*)p_caphi, (__half2*)p_caplo, TT * BB * EE / 4);
    f32_cvt_perm<<<((EE + HE) * G4 + 255) / 256, 256>>>(W_ih1, p_wh + O_IH1, EE + HE);
    f32_cvt_perm<<<(HD * G4 + 255) / 256, 256>>>(W_hh1, p_wh + O_HH1, HD);
    f32_cvt_perm<<<(HD * G4 + 255) / 256, 256>>>(W_ih2, p_wh + O_IH2, HD);
    f32_cvt_perm<<<(HD * G4 + 255) / 256, 256>>>(W_hh2, p_wh + O_HH2, HD);
    bias_prep<<<(G4 + 255) / 256, 256>>>(b_ih1, b_hh1, b_ih2, b_hh2);
    init_state<<<(BB * HD + 255) / 256, 256>>>(h1_0, c1_0, h2_0, c2_0);

    // enc_proj = enc @ att_W + att_b (fp16 out, APASS=1)
    {
        GemmArgs3 a = {};
        a.seg[0] = {p_ench, p_ench, HE, p_wh + O_ATTW, AP, HE};
        a.nseg = 1; a.ldd = AP; a.bias = att_b; a.mode = 4;
        a.Dh = p_encprojh; a.zchunk = 0;
        gemm_f16s<1><<<dim3(AP / 64, (BB * LL) / 64), 256, SMEM_BYTES>>>(a);
    }

    // full 64-step decoder loop: ONE persistent kernel
    decoder_loop<<<NCTA, 256, SMEM_BYTES>>>(corr_w, corr_b, mask, dhp_b);

    // final batched out-projection: out = tanh(h1_archive @ lt_W + lt_b), APASS=1 (leaf)
    {
        GemmArgs3 a = {};
        a.seg[0] = {p_h1ahi, p_h1alo, HD, p_wh + O_LTW, HD, HD};
        a.nseg = 1; a.D = out; a.ldd = HD; a.bias = lt_b; a.mode = 1; a.zchunk = 0;
        gemm_f16s<1><<<dim3(HD / 64, (TT * BB) / 64), 256, SMEM_BYTES>>>(a);
    }

    (void)in_sizes; (void)n_in; (void)out_size;
}